// round 2
// baseline (speedup 1.0000x reference)
#include <cuda_runtime.h>
#include <cstdint>

#define U_N 10000
#define G_N 3000
#define I_N 8000
#define D 32
#define LMEM 20
#define B_N 4096
#define NNZ_UI 720000
#define NNZ_GI 440000
#define UI_N (U_N + I_N)   /* 18000 */
#define GI_N (G_N + I_N)   /* 11000 */
#define KSPLIT 2
#define CDIV(a,b) (((a)+(b)-1)/(b))

// ----------------- scratch (static __device__ globals; no allocation) -----------------
__device__ float d_ui0[UI_N*D], d_ui1[UI_N*D], d_ui2[UI_N*D], d_ui3[UI_N*D];
__device__ float d_gi0[GI_N*D], d_gi1[GI_N*D], d_gi2[GI_N*D], d_gi3[GI_N*D];
__device__ float d_cat[GI_N*D];
__device__ float d_l1[G_N*D], d_l3[G_N*D];
__device__ int   d_cnt[UI_N];
__device__ int   d_off[UI_N+1];
__device__ int   d_cur[UI_N];
__device__ int   d_scol[NNZ_UI];
__device__ float d_sval[NNZ_UI];
__device__ float d_uemean[U_N*D], d_iemean[I_N*D];
__device__ float d_iemb[I_N*D], d_gemb[G_N*D];
__device__ float d_part0[U_N*D], d_part1[U_N*D];
__device__ float d_t1[U_N*D], d_accu[U_N*D];
__device__ float d_gul[G_N*D];
__device__ float d_wgt[2*G_N];
__device__ float d_gfin[G_N*D];
__device__ float d_it1[I_N*D], d_iacc[I_N*D];

// ----------------- elementwise helpers -----------------
__global__ void k_copy2(const float* __restrict__ a, int na,
                        const float* __restrict__ b, int nb, float* __restrict__ dst) {
  int i = blockIdx.x*blockDim.x + threadIdx.x;
  if (i < na) dst[i] = a[i];
  else if (i < na+nb) dst[i] = b[i-na];
}

__global__ void k_zero_i(int* p, int n) {
  int i = blockIdx.x*blockDim.x + threadIdx.x;
  if (i < n) p[i] = 0;
}

__global__ void k_count(const int* __restrict__ rows, int nnz, int* cnt) {
  int i = blockIdx.x*blockDim.x + threadIdx.x;
  if (i < nnz) atomicAdd(&cnt[rows[i]], 1);
}

// single-block exclusive scan (n <= ~64K)
__global__ void k_scan(const int* __restrict__ cnt, int* __restrict__ off,
                       int* __restrict__ cur, int n) {
  __shared__ int s[1024];
  __shared__ int carry_s;
  int t = threadIdx.x;
  if (t == 0) carry_s = 0;
  __syncthreads();
  for (int base = 0; base < n; base += 1024) {
    int i = base + t;
    int v = (i < n) ? cnt[i] : 0;
    s[t] = v;
    __syncthreads();
    for (int d = 1; d < 1024; d <<= 1) {
      int add = (t >= d) ? s[t-d] : 0;
      __syncthreads();
      s[t] += add;
      __syncthreads();
    }
    int carry = carry_s;
    int excl = carry + s[t] - v;
    if (i < n) { off[i] = excl; cur[i] = excl; }
    int tot = s[1023];
    __syncthreads();
    if (t == 0) carry_s = carry + tot;
    __syncthreads();
  }
  if (t == 0) off[n] = carry_s;
}

__global__ void k_scatter(const int* __restrict__ rows, const int* __restrict__ cols,
                          const float* __restrict__ vals, int nnz,
                          int* cur, int* __restrict__ scol, float* __restrict__ sval) {
  int i = blockIdx.x*blockDim.x + threadIdx.x;
  if (i < nnz) {
    int r = rows[i];
    int p = atomicAdd(&cur[r], 1);
    scol[p] = cols[i];
    sval[p] = vals[i];
  }
}

// CSR SpMM: warp per row, lane per dim
__global__ void k_spmm(const int* __restrict__ off, const int* __restrict__ scol,
                       const float* __restrict__ sval, const float* __restrict__ x,
                       float* __restrict__ y, int nrows) {
  int row = blockIdx.x*8 + (threadIdx.x >> 5);
  int lane = threadIdx.x & 31;
  if (row >= nrows) return;
  int s = off[row], e = off[row+1];
  float acc = 0.f;
  #pragma unroll 4
  for (int p = s; p < e; ++p) {
    int c = __ldg(&scol[p]);
    float v = __ldg(&sval[p]);
    acc = fmaf(v, x[c*D + lane], acc);
  }
  y[row*D + lane] = acc;
}

__global__ void k_mean_ui() {
  int i = blockIdx.x*blockDim.x + threadIdx.x;
  if (i >= UI_N*D) return;
  float m = 0.25f*(d_ui0[i] + d_ui1[i] + d_ui2[i] + d_ui3[i]);
  if (i < U_N*D) d_uemean[i] = m;
  else d_iemean[i - U_N*D] = m;
}

__global__ void k_mean_gi() {
  int i = blockIdx.x*blockDim.x + threadIdx.x;
  if (i < G_N*D)
    d_gemb[i] = 0.25f*(d_gi0[i] + d_l1[i] + d_gi2[i] + d_l3[i]);
  if (i < I_N*D) {
    int j = G_N*D + i;
    d_iemb[i] = 0.25f*(d_gi0[j] + d_gi1[j] + d_gi2[j] + d_gi3[j]);
  }
}

// ----------------- dense GEMM: Y[N,32] = A[N,K] @ X[K,32], f32x2 FMA -----------------
__global__ void __launch_bounds__(256)
k_gemm(const float* __restrict__ A, const float* __restrict__ X,
       float* __restrict__ P0, float* __restrict__ P1, int N, int K) {
  __shared__ __align__(16) float Xs[32*32*2];   // duplicated pairs {x,x} per (kk,d)
  __shared__ __align__(16) float Os[32*130];    // [kk][row 0..127] + pad2
  int tx = threadIdx.x & 31, ty = threadIdx.x >> 5;
  int rowbase = blockIdx.x * 128;
  int kchunk = (K + KSPLIT - 1) / KSPLIT;
  int kbeg = blockIdx.y * kchunk;
  int kend = min(K, kbeg + kchunk);

  unsigned long long acc[8];
  #pragma unroll
  for (int q = 0; q < 8; ++q) acc[q] = 0ULL;

  for (int k0 = kbeg; k0 < kend; k0 += 32) {
    #pragma unroll
    for (int s = 0; s < 4; ++s) {
      int e = threadIdx.x + 256*s;
      int i = e >> 5, j = e & 31;
      float v = (k0 + i < kend) ? X[(k0 + i)*D + j] : 0.f;
      Xs[(i*32 + j)*2]     = v;
      Xs[(i*32 + j)*2 + 1] = v;
    }
    #pragma unroll
    for (int s = 0; s < 16; ++s) {
      int e = threadIdx.x + 256*s;
      int r = e >> 5, c = e & 31;
      int gr = rowbase + r;
      float v = 0.f;
      if (gr < N && (k0 + c) < kend) v = A[(size_t)gr*K + (k0 + c)];
      Os[c*130 + r] = v;
    }
    __syncthreads();
    #pragma unroll
    for (int kk = 0; kk < 32; ++kk) {
      unsigned long long xb =
        *reinterpret_cast<const unsigned long long*>(&Xs[(kk*32 + tx)*2]);
      const unsigned long long* orow =
        reinterpret_cast<const unsigned long long*>(&Os[kk*130]);
      #pragma unroll
      for (int q = 0; q < 8; ++q) {
        unsigned long long ob = orow[ty + 8*q];   // rows 2*(ty+8q), 2*(ty+8q)+1
        asm("fma.rn.f32x2 %0, %1, %2, %0;" : "+l"(acc[q]) : "l"(ob), "l"(xb));
      }
    }
    __syncthreads();
  }
  float* P = (blockIdx.y == 0) ? P0 : P1;
  #pragma unroll
  for (int q = 0; q < 8; ++q) {
    int pr = ty + 8*q;
    int r0 = rowbase + 2*pr;
    float lo = __uint_as_float((unsigned)(acc[q] & 0xffffffffULL));
    float hi = __uint_as_float((unsigned)(acc[q] >> 32));
    if (r0     < N) P[(size_t)r0*D + tx]     = lo;
    if (r0 + 1 < N) P[(size_t)(r0+1)*D + tx] = hi;
  }
}

__global__ void k_add2(const float* __restrict__ p0, const float* __restrict__ p1,
                       float* __restrict__ y, int n) {
  int i = blockIdx.x*blockDim.x + threadIdx.x;
  if (i < n) y[i] = p0[i] + p1[i];
}

__global__ void k_add4(const float* __restrict__ base, const float* __restrict__ t,
                       const float* __restrict__ p0, const float* __restrict__ p1,
                       float* __restrict__ y, int n) {
  int i = blockIdx.x*blockDim.x + threadIdx.x;
  if (i < n) y[i] = base[i] + t[i] + p0[i] + p1[i];
}

// group_userlayer[g,d] = sum_l mask[g,l] * acc_u[users[g,l], d]
__global__ void k_gul(const int* __restrict__ gu, const float* __restrict__ gm) {
  int g = blockIdx.x*8 + (threadIdx.x >> 5);
  int lane = threadIdx.x & 31;
  if (g >= G_N) return;
  float acc = 0.f;
  #pragma unroll
  for (int l = 0; l < LMEM; ++l) {
    int u = __ldg(&gu[g*LMEM + l]);
    float m = __ldg(&gm[g*LMEM + l]);
    acc = fmaf(m, d_accu[u*D + lane], acc);
  }
  d_gul[g*D + lane] = acc;
}

// gate: per-row [2G,32] @ W1 -> relu -> @ w2 -> sigmoid
__global__ void k_gate(const float* __restrict__ w1, const float* __restrict__ b1,
                       const float* __restrict__ w2, const float* __restrict__ b2) {
  int row = blockIdx.x*8 + (threadIdx.x >> 5);
  int lane = threadIdx.x & 31;
  if (row >= 2*G_N) return;
  const float* x = (row < G_N) ? &d_gemb[row*D] : &d_gul[(row - G_N)*D];
  float xv = x[lane];
  float h = b1[lane];
  #pragma unroll
  for (int k = 0; k < 32; ++k) {
    float xk = __shfl_sync(0xffffffffu, xv, k);
    h = fmaf(xk, w1[k*D + lane], h);
  }
  h = fmaxf(h, 0.f);
  float s = h * w2[lane];
  #pragma unroll
  for (int o = 16; o > 0; o >>= 1) s += __shfl_xor_sync(0xffffffffu, s, o);
  if (lane == 0) d_wgt[row] = 1.f/(1.f + expf(-(s + b2[0])));
}

__global__ void k_gfin() {
  int i = blockIdx.x*blockDim.x + threadIdx.x;
  if (i >= G_N*D) return;
  int g = i / D;
  d_gfin[i] = d_wgt[g]*d_gemb[i] + d_wgt[G_N + g]*d_gul[i];
}

__global__ void k_pred(const int* __restrict__ gin, const int* __restrict__ iin,
                       const float* __restrict__ w1, const float* __restrict__ b1,
                       const float* __restrict__ w2, const float* __restrict__ b2,
                       float* __restrict__ out) {
  int b = blockIdx.x*8 + (threadIdx.x >> 5);
  int lane = threadIdx.x & 31;
  if (b >= B_N) return;
  float e = d_gfin[gin[b]*D + lane] * d_iacc[iin[b]*D + lane];
  float z = 0.f;
  #pragma unroll
  for (int j = 0; j < 8; ++j) {
    float v = e * w1[lane*8 + j];
    #pragma unroll
    for (int o = 16; o > 0; o >>= 1) v += __shfl_xor_sync(0xffffffffu, v, o);
    if (lane == 0) z += fmaxf(v + b1[j], 0.f) * w2[j];
  }
  if (lane == 0) out[b] = 1.f/(1.f + expf(-(z + b2[0])));
}

// ----------------- host -----------------
template <typename T>
static T* symaddr(const void* sym) {
  void* p = nullptr;
  cudaGetSymbolAddress(&p, sym);
  return (T*)p;
}

extern "C" void kernel_launch(void* const* d_in, const int* in_sizes, int n_in,
                              void* d_out, int out_size) {
  const int*   gin       = (const int*)d_in[0];
  const int*   iin       = (const int*)d_in[1];
  const float* user_emb  = (const float*)d_in[2];
  const float* group_emb = (const float*)d_in[3];
  const float* item_emb  = (const float*)d_in[4];
  const int*   ui_rows   = (const int*)d_in[5];
  const int*   ui_cols   = (const int*)d_in[6];
  const float* ui_vals   = (const float*)d_in[7];
  const int*   gi_rows   = (const int*)d_in[8];
  const int*   gi_cols   = (const int*)d_in[9];
  const float* gi_vals   = (const float*)d_in[10];
  const float* ov_user   = (const float*)d_in[11];
  const float* ov_item   = (const float*)d_in[12];
  const int*   agu       = (const int*)d_in[13];
  const float* agm       = (const float*)d_in[14];
  const float* gate_w1   = (const float*)d_in[15];
  const float* gate_b1   = (const float*)d_in[16];
  const float* gate_w2   = (const float*)d_in[17];
  const float* gate_b2   = (const float*)d_in[18];
  const float* pred_w1   = (const float*)d_in[19];
  const float* pred_b1   = (const float*)d_in[20];
  const float* pred_w2   = (const float*)d_in[21];
  const float* pred_b2   = (const float*)d_in[22];
  float* out = (float*)d_out;

  float *p_ui0 = symaddr<float>(d_ui0), *p_ui1 = symaddr<float>(d_ui1);
  float *p_ui2 = symaddr<float>(d_ui2), *p_ui3 = symaddr<float>(d_ui3);
  float *p_gi0 = symaddr<float>(d_gi0), *p_gi1 = symaddr<float>(d_gi1);
  float *p_gi2 = symaddr<float>(d_gi2), *p_gi3 = symaddr<float>(d_gi3);
  float *p_cat = symaddr<float>(d_cat);
  float *p_l1  = symaddr<float>(d_l1),  *p_l3  = symaddr<float>(d_l3);
  int   *p_cnt = symaddr<int>(d_cnt), *p_off = symaddr<int>(d_off), *p_cur = symaddr<int>(d_cur);
  int   *p_scol = symaddr<int>(d_scol);
  float *p_sval = symaddr<float>(d_sval);
  float *p_uemean = symaddr<float>(d_uemean), *p_iemean = symaddr<float>(d_iemean);
  float *p_iemb = symaddr<float>(d_iemb);
  float *p_p0 = symaddr<float>(d_part0), *p_p1 = symaddr<float>(d_part1);
  float *p_t1 = symaddr<float>(d_t1), *p_accu = symaddr<float>(d_accu);
  float *p_it1 = symaddr<float>(d_it1), *p_iacc = symaddr<float>(d_iacc);

  // ---- Stage A: user-item propagation ----
  k_copy2<<<CDIV((U_N+I_N)*D,256),256>>>(user_emb, U_N*D, item_emb, I_N*D, p_ui0);
  k_zero_i<<<CDIV(UI_N,256),256>>>(p_cnt, UI_N);
  k_count<<<CDIV(NNZ_UI,256),256>>>(ui_rows, NNZ_UI, p_cnt);
  k_scan<<<1,1024>>>(p_cnt, p_off, p_cur, UI_N);
  k_scatter<<<CDIV(NNZ_UI,256),256>>>(ui_rows, ui_cols, ui_vals, NNZ_UI, p_cur, p_scol, p_sval);
  k_spmm<<<CDIV(UI_N,8),256>>>(p_off, p_scol, p_sval, p_ui0, p_ui1, UI_N);
  k_spmm<<<CDIV(UI_N,8),256>>>(p_off, p_scol, p_sval, p_ui1, p_ui2, UI_N);
  k_spmm<<<CDIV(UI_N,8),256>>>(p_off, p_scol, p_sval, p_ui2, p_ui3, UI_N);
  k_mean_ui<<<CDIV(UI_N*D,256),256>>>();

  // ---- Stage B: group-item propagation ----
  k_copy2<<<CDIV(GI_N*D,256),256>>>(group_emb, G_N*D, p_iemean, I_N*D, p_gi0);
  k_zero_i<<<CDIV(GI_N,256),256>>>(p_cnt, GI_N);
  k_count<<<CDIV(NNZ_GI,256),256>>>(gi_rows, NNZ_GI, p_cnt);
  k_scan<<<1,1024>>>(p_cnt, p_off, p_cur, GI_N);
  k_scatter<<<CDIV(NNZ_GI,256),256>>>(gi_rows, gi_cols, gi_vals, NNZ_GI, p_cur, p_scol, p_sval);
  k_spmm<<<CDIV(GI_N,8),256>>>(p_off, p_scol, p_sval, p_gi0, p_gi1, GI_N);
  k_spmm<<<CDIV(GI_N,8),256>>>(p_off, p_scol, p_sval, p_gi1, p_gi2, GI_N);
  k_spmm<<<CDIV(GI_N,8),256>>>(p_off, p_scol, p_sval, p_gi2, p_gi3, GI_N);
  // g_layers odd terms (only first G rows needed)
  k_copy2<<<CDIV(GI_N*D,256),256>>>(group_emb, G_N*D, item_emb, I_N*D, p_cat);
  k_spmm<<<CDIV(G_N,8),256>>>(p_off, p_scol, p_sval, p_cat, p_l1, G_N);
  k_copy2<<<CDIV(GI_N*D,256),256>>>(group_emb, G_N*D, p_ui2 + U_N*D, I_N*D, p_cat);
  k_spmm<<<CDIV(G_N,8),256>>>(p_off, p_scol, p_sval, p_cat, p_l3, G_N);
  k_mean_gi<<<CDIV(I_N*D,256),256>>>();

  // ---- Stage C: social user (dense power series) ----
  dim3 gu(CDIV(U_N,128), KSPLIT);
  k_gemm<<<gu,256>>>(ov_user, p_uemean, p_p0, p_p1, U_N, U_N);
  k_add2<<<CDIV(U_N*D,256),256>>>(p_p0, p_p1, p_t1, U_N*D);
  k_gemm<<<gu,256>>>(ov_user, p_t1, p_p0, p_p1, U_N, U_N);
  k_add4<<<CDIV(U_N*D,256),256>>>(p_uemean, p_t1, p_p0, p_p1, p_accu, U_N*D);
  k_gul<<<CDIV(G_N,8),256>>>(agu, agm);

  // ---- Stage D: gate + final group embedding ----
  k_gate<<<CDIV(2*G_N,8),256>>>(gate_w1, gate_b1, gate_w2, gate_b2);
  k_gfin<<<CDIV(G_N*D,256),256>>>();

  // ---- Stage E: social items ----
  dim3 gi(CDIV(I_N,128), KSPLIT);
  k_gemm<<<gi,256>>>(ov_item, p_iemb, p_p0, p_p1, I_N, I_N);
  k_add2<<<CDIV(I_N*D,256),256>>>(p_p0, p_p1, p_it1, I_N*D);
  k_gemm<<<gi,256>>>(ov_item, p_it1, p_p0, p_p1, I_N, I_N);
  k_add4<<<CDIV(I_N*D,256),256>>>(p_iemb, p_it1, p_p0, p_p1, p_iacc, I_N*D);

  // ---- Stage F: predict ----
  k_pred<<<CDIV(B_N,8),256>>>(gin, iin, pred_w1, pred_b1, pred_w2, pred_b2, out);
}

// round 3
// speedup vs baseline: 2.6187x; 2.6187x over previous
#include <cuda_runtime.h>
#include <cstdint>

#define U_N 10000
#define G_N 3000
#define I_N 8000
#define D 32
#define LMEM 20
#define B_N 4096
#define NNZ_UI 720000
#define NNZ_GI 440000
#define UI_N (U_N + I_N)   /* 18000 */
#define GI_N (G_N + I_N)   /* 11000 */
#define KS 8               /* k-split for GEMM */
#define BR 256             /* rows per GEMM tile */
#define CDIV(a,b) (((a)+(b)-1)/(b))

// A-tile row stride in floats (pad 32 -> 36 for smem)
#define ASTRIDE 36
#define SMEM_GEMM ((2*BR*ASTRIDE + 2*32*32) * 4)

// ----------------- scratch (static __device__ globals) -----------------
__device__ float d_ui0[UI_N*D], d_ui1[UI_N*D], d_ui2[UI_N*D], d_ui3[UI_N*D];
__device__ float d_gi0[GI_N*D], d_gi1[GI_N*D], d_gi2[GI_N*D], d_gi3[GI_N*D];
__device__ float d_cat[GI_N*D];
__device__ float d_l1[G_N*D], d_l3[G_N*D];
__device__ int   d_cnt[UI_N];
__device__ int   d_off[UI_N+1];
__device__ int   d_cur[UI_N];
__device__ int   d_scol[NNZ_UI];
__device__ float d_sval[NNZ_UI];
__device__ float d_uemean[U_N*D], d_iemean[I_N*D];
__device__ float d_iemb[I_N*D], d_gemb[G_N*D];
__device__ float d_parts[KS*U_N*D];          // k-split partials (41 MB)
__device__ float d_t1[U_N*D], d_accu[U_N*D];
__device__ float d_gul[G_N*D];
__device__ float d_wgt[2*G_N];
__device__ float d_gfin[G_N*D];
__device__ float d_it1[I_N*D], d_iacc[I_N*D];

// ----------------- small helpers -----------------
__global__ void k_copy2(const float* __restrict__ a, int na,
                        const float* __restrict__ b, int nb, float* __restrict__ dst) {
  int i = blockIdx.x*blockDim.x + threadIdx.x;
  if (i < na) dst[i] = a[i];
  else if (i < na+nb) dst[i] = b[i-na];
}

// fused: concat-copy into dst AND zero the count array
__global__ void k_copy_zero(const float* __restrict__ a, int na,
                            const float* __restrict__ b, int nb,
                            float* __restrict__ dst, int* __restrict__ cnt, int ncnt) {
  int i = blockIdx.x*blockDim.x + threadIdx.x;
  if (i < na) dst[i] = a[i];
  else if (i < na+nb) dst[i] = b[i-na];
  if (i < ncnt) cnt[i] = 0;
}

__global__ void k_count(const int* __restrict__ rows, int nnz, int* cnt) {
  int i = blockIdx.x*blockDim.x + threadIdx.x;
  if (i < nnz) atomicAdd(&cnt[rows[i]], 1);
}

// single-block warp-shuffle exclusive scan (fast)
__global__ void __launch_bounds__(1024)
k_scan(const int* __restrict__ cnt, int* __restrict__ off,
       int* __restrict__ cur, int n) {
  __shared__ int warptot[32];
  int t = threadIdx.x;
  int lane = t & 31, w = t >> 5;
  int per = (n + 1023) / 1024;
  int beg = t * per, end = min(n, beg + per);
  int s = 0;
  for (int i = beg; i < end; ++i) s += cnt[i];
  // inclusive warp scan of s
  int v = s;
  #pragma unroll
  for (int o = 1; o < 32; o <<= 1) {
    int u = __shfl_up_sync(0xffffffffu, v, o);
    if (lane >= o) v += u;
  }
  if (lane == 31) warptot[w] = v;
  __syncthreads();
  if (w == 0) {
    int x = warptot[lane];
    #pragma unroll
    for (int o = 1; o < 32; o <<= 1) {
      int u = __shfl_up_sync(0xffffffffu, x, o);
      if (lane >= o) x += u;
    }
    warptot[lane] = x;   // inclusive over warps
  }
  __syncthreads();
  int base = (w ? warptot[w-1] : 0) + v - s;   // exclusive prefix for this thread
  int run = base;
  for (int i = beg; i < end; ++i) {
    int c = cnt[i];
    off[i] = run; cur[i] = run;
    run += c;
  }
  if (t == 0) off[n] = warptot[31];
}

__global__ void k_scatter(const int* __restrict__ rows, const int* __restrict__ cols,
                          const float* __restrict__ vals, int nnz,
                          int* cur, int* __restrict__ scol, float* __restrict__ sval) {
  int i = blockIdx.x*blockDim.x + threadIdx.x;
  if (i < nnz) {
    int r = rows[i];
    int p = atomicAdd(&cur[r], 1);
    scol[p] = cols[i];
    sval[p] = vals[i];
  }
}

// CSR SpMM: warp per row, lane per dim
__global__ void k_spmm(const int* __restrict__ off, const int* __restrict__ scol,
                       const float* __restrict__ sval, const float* __restrict__ x,
                       float* __restrict__ y, int nrows) {
  int row = blockIdx.x*8 + (threadIdx.x >> 5);
  int lane = threadIdx.x & 31;
  if (row >= nrows) return;
  int s = off[row], e = off[row+1];
  float acc = 0.f;
  #pragma unroll 4
  for (int p = s; p < e; ++p) {
    int c = __ldg(&scol[p]);
    float v = __ldg(&sval[p]);
    acc = fmaf(v, x[c*D + lane], acc);
  }
  y[row*D + lane] = acc;
}

__global__ void k_mean_ui() {
  int i = blockIdx.x*blockDim.x + threadIdx.x;
  if (i >= UI_N*D) return;
  float m = 0.25f*(d_ui0[i] + d_ui1[i] + d_ui2[i] + d_ui3[i]);
  if (i < U_N*D) d_uemean[i] = m;
  else d_iemean[i - U_N*D] = m;
}

__global__ void k_mean_gi() {
  int i = blockIdx.x*blockDim.x + threadIdx.x;
  if (i < G_N*D)
    d_gemb[i] = 0.25f*(d_gi0[i] + d_l1[i] + d_gi2[i] + d_l3[i]);
  if (i < I_N*D) {
    int j = G_N*D + i;
    d_iemb[i] = 0.25f*(d_gi0[j] + d_gi1[j] + d_gi2[j] + d_gi3[j]);
  }
}

// ----------------- dense GEMM: P_y[N,32] = A[N, kslice_y] @ X[kslice_y, 32] -----------------
// 256 threads, 256-row x 32-d tile, BK=32, cp.async double buffer.
// Thread (g = tid%64, dg = tid/64): rows {g, g+64, g+128, g+192}, d = [8*dg, 8*dg+8).
// Accumulators: 16 x f32x2 (4 rows x 4 d-pairs).

__device__ __forceinline__ void cpa16(uint32_t dst, const void* src, int bytes) {
  asm volatile("cp.async.cg.shared.global [%0], [%1], 16, %2;"
               :: "r"(dst), "l"(src), "r"(bytes));
}
__device__ __forceinline__ void cpa_commit() {
  asm volatile("cp.async.commit_group;");
}
__device__ __forceinline__ void cpa_wait1() {
  asm volatile("cp.async.wait_group 1;");
}

extern "C" __global__ void __launch_bounds__(256, 2)
k_gemm(const float* __restrict__ A, const float* __restrict__ X,
       float* __restrict__ Pbase, size_t pstride, int N, int K) {
  extern __shared__ float smem[];
  float* As = smem;                         // [2][BR][ASTRIDE]
  float* Xs = smem + 2*BR*ASTRIDE;          // [2][32][32]

  int tid = threadIdx.x;
  int g = tid & 63, dg = tid >> 6;
  int rowbase = blockIdx.x * BR;
  int kchunk = (K + KS - 1) / KS;
  int kbeg = blockIdx.y * kchunk;
  int kend = min(K, kbeg + kchunk);
  int nch = (kend - kbeg + 31) >> 5;

  uint32_t as_u32, xs_u32;
  {
    uint32_t base;
    asm("{ .reg .u64 t; cvta.to.shared.u64 t, %1; cvt.u32.u64 %0, t; }"
        : "=r"(base) : "l"(smem));
    as_u32 = base;
    xs_u32 = base + 2*BR*ASTRIDE*4;
  }

  unsigned long long acc[4][4];
  #pragma unroll
  for (int j = 0; j < 4; ++j)
    #pragma unroll
    for (int p = 0; p < 4; ++p) acc[j][p] = 0ULL;

  // loader for one chunk into buffer b
  auto load_chunk = [&](int b, int k0) {
    // A: 2048 16B-chunks, 8 per thread
    #pragma unroll
    for (int s = 0; s < 8; ++s) {
      int id = tid + 256*s;
      int row = id >> 3, c = id & 7;
      int gr = rowbase + row;
      int kk = k0 + 4*c;
      int vb = 0;
      const float* src = A;
      if (gr < N && kk < kend) {
        vb = min(4, kend - kk) * 4;
        src = A + (size_t)gr*K + kk;
      }
      cpa16(as_u32 + (uint32_t)(b*BR*ASTRIDE + row*ASTRIDE + 4*c)*4, src, vb);
    }
    // X: 256 16B-chunks, 1 per thread
    {
      int kk = tid >> 3, c = tid & 7;
      int gk = k0 + kk;
      int vb = 0;
      const float* src = X;
      if (gk < kend) { vb = 16; src = X + (size_t)gk*D + 4*c; }
      cpa16(xs_u32 + (uint32_t)(2*BR*ASTRIDE*0 + b*32*32 + kk*32 + 4*c)*4, src, vb);
    }
  };

  if (nch > 0) load_chunk(0, kbeg);
  cpa_commit();

  for (int i = 0; i < nch; ++i) {
    if (i + 1 < nch) load_chunk((i+1) & 1, kbeg + (i+1)*32);
    cpa_commit();
    cpa_wait1();
    __syncthreads();

    const float* Ab = As + (i & 1)*BR*ASTRIDE;
    const float* Xb = Xs + (i & 1)*32*32;

    #pragma unroll
    for (int kk4 = 0; kk4 < 8; ++kk4) {
      float4 af[4];
      #pragma unroll
      for (int j = 0; j < 4; ++j)
        af[j] = *reinterpret_cast<const float4*>(&Ab[(g + 64*j)*ASTRIDE + kk4*4]);
      #pragma unroll
      for (int t = 0; t < 4; ++t) {
        int kk = kk4*4 + t;
        ulonglong2 x01 = *reinterpret_cast<const ulonglong2*>(&Xb[kk*32 + dg*8]);
        ulonglong2 x23 = *reinterpret_cast<const ulonglong2*>(&Xb[kk*32 + dg*8 + 4]);
        #pragma unroll
        for (int j = 0; j < 4; ++j) {
          float a = (t == 0) ? af[j].x : (t == 1) ? af[j].y : (t == 2) ? af[j].z : af[j].w;
          unsigned long long aa;
          asm("mov.b64 %0, {%1, %1};" : "=l"(aa) : "f"(a));
          asm("fma.rn.f32x2 %0, %1, %2, %0;" : "+l"(acc[j][0]) : "l"(aa), "l"(x01.x));
          asm("fma.rn.f32x2 %0, %1, %2, %0;" : "+l"(acc[j][1]) : "l"(aa), "l"(x01.y));
          asm("fma.rn.f32x2 %0, %1, %2, %0;" : "+l"(acc[j][2]) : "l"(aa), "l"(x23.x));
          asm("fma.rn.f32x2 %0, %1, %2, %0;" : "+l"(acc[j][3]) : "l"(aa), "l"(x23.y));
        }
      }
    }
    __syncthreads();
  }

  float* P = Pbase + (size_t)blockIdx.y * pstride;
  #pragma unroll
  for (int j = 0; j < 4; ++j) {
    int r = rowbase + g + 64*j;
    if (r < N) {
      ulonglong2 v0; v0.x = acc[j][0]; v0.y = acc[j][1];
      ulonglong2 v1; v1.x = acc[j][2]; v1.y = acc[j][3];
      *reinterpret_cast<ulonglong2*>(&P[(size_t)r*D + dg*8])     = v0;
      *reinterpret_cast<ulonglong2*>(&P[(size_t)r*D + dg*8 + 4]) = v1;
    }
  }
}

// reduce KS partials (+ up to two extra addends) into dst
__global__ void k_red(float* __restrict__ dst, const float* __restrict__ b0,
                      const float* __restrict__ b1, const float* __restrict__ parts,
                      size_t pstride, int n) {
  int i = blockIdx.x*blockDim.x + threadIdx.x;
  if (i >= n) return;
  float s = 0.f;
  #pragma unroll
  for (int p = 0; p < KS; ++p) s += parts[(size_t)p*pstride + i];
  if (b0) s += b0[i];
  if (b1) s += b1[i];
  dst[i] = s;
}

// group_userlayer[g,d] = sum_l mask[g,l] * acc_u[users[g,l], d]
__global__ void k_gul(const int* __restrict__ gu, const float* __restrict__ gm) {
  int g = blockIdx.x*8 + (threadIdx.x >> 5);
  int lane = threadIdx.x & 31;
  if (g >= G_N) return;
  float acc = 0.f;
  #pragma unroll
  for (int l = 0; l < LMEM; ++l) {
    int u = __ldg(&gu[g*LMEM + l]);
    float m = __ldg(&gm[g*LMEM + l]);
    acc = fmaf(m, d_accu[u*D + lane], acc);
  }
  d_gul[g*D + lane] = acc;
}

__global__ void k_gate(const float* __restrict__ w1, const float* __restrict__ b1,
                       const float* __restrict__ w2, const float* __restrict__ b2) {
  int row = blockIdx.x*8 + (threadIdx.x >> 5);
  int lane = threadIdx.x & 31;
  if (row >= 2*G_N) return;
  const float* x = (row < G_N) ? &d_gemb[row*D] : &d_gul[(row - G_N)*D];
  float xv = x[lane];
  float h = b1[lane];
  #pragma unroll
  for (int k = 0; k < 32; ++k) {
    float xk = __shfl_sync(0xffffffffu, xv, k);
    h = fmaf(xk, w1[k*D + lane], h);
  }
  h = fmaxf(h, 0.f);
  float s = h * w2[lane];
  #pragma unroll
  for (int o = 16; o > 0; o >>= 1) s += __shfl_xor_sync(0xffffffffu, s, o);
  if (lane == 0) d_wgt[row] = 1.f/(1.f + expf(-(s + b2[0])));
}

__global__ void k_gfin() {
  int i = blockIdx.x*blockDim.x + threadIdx.x;
  if (i >= G_N*D) return;
  int g = i / D;
  d_gfin[i] = d_wgt[g]*d_gemb[i] + d_wgt[G_N + g]*d_gul[i];
}

__global__ void k_pred(const int* __restrict__ gin, const int* __restrict__ iin,
                       const float* __restrict__ w1, const float* __restrict__ b1,
                       const float* __restrict__ w2, const float* __restrict__ b2,
                       float* __restrict__ out) {
  int b = blockIdx.x*8 + (threadIdx.x >> 5);
  int lane = threadIdx.x & 31;
  if (b >= B_N) return;
  float e = d_gfin[gin[b]*D + lane] * d_iacc[iin[b]*D + lane];
  float z = 0.f;
  #pragma unroll
  for (int j = 0; j < 8; ++j) {
    float v = e * w1[lane*8 + j];
    #pragma unroll
    for (int o = 16; o > 0; o >>= 1) v += __shfl_xor_sync(0xffffffffu, v, o);
    if (lane == 0) z += fmaxf(v + b1[j], 0.f) * w2[j];
  }
  if (lane == 0) out[b] = 1.f/(1.f + expf(-(z + b2[0])));
}

// ----------------- host -----------------
template <typename T>
static T* symaddr(const void* sym) {
  void* p = nullptr;
  cudaGetSymbolAddress(&p, sym);
  return (T*)p;
}

extern "C" void kernel_launch(void* const* d_in, const int* in_sizes, int n_in,
                              void* d_out, int out_size) {
  const int*   gin       = (const int*)d_in[0];
  const int*   iin       = (const int*)d_in[1];
  const float* user_emb  = (const float*)d_in[2];
  const float* group_emb = (const float*)d_in[3];
  const float* item_emb  = (const float*)d_in[4];
  const int*   ui_rows   = (const int*)d_in[5];
  const int*   ui_cols   = (const int*)d_in[6];
  const float* ui_vals   = (const float*)d_in[7];
  const int*   gi_rows   = (const int*)d_in[8];
  const int*   gi_cols   = (const int*)d_in[9];
  const float* gi_vals   = (const float*)d_in[10];
  const float* ov_user   = (const float*)d_in[11];
  const float* ov_item   = (const float*)d_in[12];
  const int*   agu       = (const int*)d_in[13];
  const float* agm       = (const float*)d_in[14];
  const float* gate_w1   = (const float*)d_in[15];
  const float* gate_b1   = (const float*)d_in[16];
  const float* gate_w2   = (const float*)d_in[17];
  const float* gate_b2   = (const float*)d_in[18];
  const float* pred_w1   = (const float*)d_in[19];
  const float* pred_b1   = (const float*)d_in[20];
  const float* pred_w2   = (const float*)d_in[21];
  const float* pred_b2   = (const float*)d_in[22];
  float* out = (float*)d_out;

  cudaFuncSetAttribute(k_gemm, cudaFuncAttributeMaxDynamicSharedMemorySize, SMEM_GEMM);

  float *p_ui0 = symaddr<float>(d_ui0), *p_ui1 = symaddr<float>(d_ui1);
  float *p_ui2 = symaddr<float>(d_ui2), *p_ui3 = symaddr<float>(d_ui3);
  float *p_gi0 = symaddr<float>(d_gi0), *p_gi1 = symaddr<float>(d_gi1);
  float *p_gi2 = symaddr<float>(d_gi2), *p_gi3 = symaddr<float>(d_gi3);
  float *p_cat = symaddr<float>(d_cat);
  float *p_l1  = symaddr<float>(d_l1),  *p_l3  = symaddr<float>(d_l3);
  int   *p_cnt = symaddr<int>(d_cnt), *p_off = symaddr<int>(d_off), *p_cur = symaddr<int>(d_cur);
  int   *p_scol = symaddr<int>(d_scol);
  float *p_sval = symaddr<float>(d_sval);
  float *p_uemean = symaddr<float>(d_uemean), *p_iemean = symaddr<float>(d_iemean);
  float *p_iemb = symaddr<float>(d_iemb);
  float *p_parts = symaddr<float>(d_parts);
  float *p_t1 = symaddr<float>(d_t1), *p_accu = symaddr<float>(d_accu);
  float *p_it1 = symaddr<float>(d_it1), *p_iacc = symaddr<float>(d_iacc);

  const size_t PSTRIDE = (size_t)U_N * D;
  dim3 gemm_u(CDIV(U_N, BR), KS);
  dim3 gemm_i(CDIV(I_N, BR), KS);

  // ---- Stage A: user-item propagation ----
  // launches: 1..5, then a representative GEMM as launch 6 (for ncu -s 5 -c 1)
  k_copy_zero<<<CDIV((U_N+I_N)*D,256),256>>>(user_emb, U_N*D, item_emb, I_N*D, p_ui0, p_cnt, UI_N);
  k_count<<<CDIV(NNZ_UI,256),256>>>(ui_rows, NNZ_UI, p_cnt);
  k_scan<<<1,1024>>>(p_cnt, p_off, p_cur, UI_N);
  k_scatter<<<CDIV(NNZ_UI,256),256>>>(ui_rows, ui_cols, ui_vals, NNZ_UI, p_cur, p_scol, p_sval);
  k_spmm<<<CDIV(UI_N,8),256>>>(p_off, p_scol, p_sval, p_ui0, p_ui1, UI_N);
  // launch #6: representative GEMM on real ov_user data (K truncated), output overwritten later.
  k_gemm<<<gemm_u,256,SMEM_GEMM>>>(ov_user, ov_user, p_parts, PSTRIDE, U_N, 2496);
  k_spmm<<<CDIV(UI_N,8),256>>>(p_off, p_scol, p_sval, p_ui1, p_ui2, UI_N);
  k_spmm<<<CDIV(UI_N,8),256>>>(p_off, p_scol, p_sval, p_ui2, p_ui3, UI_N);
  k_mean_ui<<<CDIV(UI_N*D,256),256>>>();

  // ---- Stage C: social user (dense power series) ----
  k_gemm<<<gemm_u,256,SMEM_GEMM>>>(ov_user, p_uemean, p_parts, PSTRIDE, U_N, U_N);
  k_red<<<CDIV(U_N*D,256),256>>>(p_t1, nullptr, nullptr, p_parts, PSTRIDE, U_N*D);
  k_gemm<<<gemm_u,256,SMEM_GEMM>>>(ov_user, p_t1, p_parts, PSTRIDE, U_N, U_N);
  k_red<<<CDIV(U_N*D,256),256>>>(p_accu, p_uemean, p_t1, p_parts, PSTRIDE, U_N*D);
  k_gul<<<CDIV(G_N,8),256>>>(agu, agm);

  // ---- Stage B: group-item propagation ----
  k_copy_zero<<<CDIV(GI_N*D,256),256>>>(group_emb, G_N*D, p_iemean, I_N*D, p_gi0, p_cnt, GI_N);
  k_count<<<CDIV(NNZ_GI,256),256>>>(gi_rows, NNZ_GI, p_cnt);
  k_scan<<<1,1024>>>(p_cnt, p_off, p_cur, GI_N);
  k_scatter<<<CDIV(NNZ_GI,256),256>>>(gi_rows, gi_cols, gi_vals, NNZ_GI, p_cur, p_scol, p_sval);
  k_spmm<<<CDIV(GI_N,8),256>>>(p_off, p_scol, p_sval, p_gi0, p_gi1, GI_N);
  k_spmm<<<CDIV(GI_N,8),256>>>(p_off, p_scol, p_sval, p_gi1, p_gi2, GI_N);
  k_spmm<<<CDIV(GI_N,8),256>>>(p_off, p_scol, p_sval, p_gi2, p_gi3, GI_N);
  // g_layers odd terms (only first G rows needed)
  k_copy2<<<CDIV(GI_N*D,256),256>>>(group_emb, G_N*D, item_emb, I_N*D, p_cat);
  k_spmm<<<CDIV(G_N,8),256>>>(p_off, p_scol, p_sval, p_cat, p_l1, G_N);
  k_copy2<<<CDIV(GI_N*D,256),256>>>(group_emb, G_N*D, p_ui2 + U_N*D, I_N*D, p_cat);
  k_spmm<<<CDIV(G_N,8),256>>>(p_off, p_scol, p_sval, p_cat, p_l3, G_N);
  k_mean_gi<<<CDIV(I_N*D,256),256>>>();

  // ---- Stage D: gate + final group embedding ----
  k_gate<<<CDIV(2*G_N,8),256>>>(gate_w1, gate_b1, gate_w2, gate_b2);
  k_gfin<<<CDIV(G_N*D,256),256>>>();

  // ---- Stage E: social items ----
  k_gemm<<<gemm_i,256,SMEM_GEMM>>>(ov_item, p_iemb, p_parts, PSTRIDE, I_N, I_N);
  k_red<<<CDIV(I_N*D,256),256>>>(p_it1, nullptr, nullptr, p_parts, PSTRIDE, I_N*D);
  k_gemm<<<gemm_i,256,SMEM_GEMM>>>(ov_item, p_it1, p_parts, PSTRIDE, I_N, I_N);
  k_red<<<CDIV(I_N*D,256),256>>>(p_iacc, p_iemb, p_it1, p_parts, PSTRIDE, I_N*D);

  // ---- Stage F: predict ----
  k_pred<<<CDIV(B_N,8),256>>>(gin, iin, pred_w1, pred_b1, pred_w2, pred_b2, out);
}

// round 4
// speedup vs baseline: 3.3679x; 1.2861x over previous
#include <cuda_runtime.h>
#include <cstdint>

#define U_N 10000
#define G_N 3000
#define I_N 8000
#define D 32
#define LMEM 20
#define B_N 4096
#define NNZ_UI 720000
#define NNZ_GI 440000
#define UI_N (U_N + I_N)   /* 18000 */
#define GI_N (G_N + I_N)   /* 11000 */
#define KSU 7              /* k-split: 40x7=280 blocks (<1 wave @2/SM) */
#define KSI 9              /* k-split: 32x9=288 blocks */
#define BR 256             /* rows per GEMM tile */
#define CDIV(a,b) (((a)+(b)-1)/(b))

#define ASTRIDE 36
#define SMEM_GEMM ((2*BR*ASTRIDE + 2*32*32) * 4)

// ----------------- scratch -----------------
__device__ float d_ui0[UI_N*D], d_ui1[UI_N*D], d_ui2[UI_N*D], d_ui3[UI_N*D];
__device__ float d_gi0[GI_N*D], d_gi1[GI_N*D], d_gi2[GI_N*D], d_gi3[GI_N*D];
__device__ float d_cat[GI_N*D], d_cat2[GI_N*D];
__device__ float d_l1[G_N*D], d_l3[G_N*D];
// UI CSR
__device__ int   d_cnt[UI_N];
__device__ int   d_off[UI_N+1];
__device__ int   d_cur[UI_N];
__device__ int   d_scol[NNZ_UI];
__device__ float d_sval[NNZ_UI];
// GI CSR (separate so it can build concurrently)
__device__ int   d_cnt2[GI_N];
__device__ int   d_off2[GI_N+1];
__device__ int   d_cur2[GI_N];
__device__ int   d_scol2[NNZ_GI];
__device__ float d_sval2[NNZ_GI];

__device__ float d_uemean[U_N*D], d_iemean[I_N*D];
__device__ float d_iemb[I_N*D], d_gemb[G_N*D];
__device__ float d_parts[KSU*U_N*D];
__device__ float d_parts2[KSI*I_N*D];
__device__ float d_t1[U_N*D], d_accu[U_N*D];
__device__ float d_gul[G_N*D];
__device__ float d_wgt[2*G_N];
__device__ float d_gfin[G_N*D];
__device__ float d_it1[I_N*D], d_iacc[I_N*D];

// ----------------- small helpers -----------------
__global__ void k_copy2(const float* __restrict__ a, int na,
                        const float* __restrict__ b, int nb, float* __restrict__ dst) {
  int i = blockIdx.x*blockDim.x + threadIdx.x;
  if (i < na) dst[i] = a[i];
  else if (i < na+nb) dst[i] = b[i-na];
}

__global__ void k_copy_zero(const float* __restrict__ a, int na,
                            const float* __restrict__ b, int nb,
                            float* __restrict__ dst, int* __restrict__ cnt, int ncnt) {
  int i = blockIdx.x*blockDim.x + threadIdx.x;
  if (i < na) dst[i] = a[i];
  else if (i < na+nb) dst[i] = b[i-na];
  if (i < ncnt) cnt[i] = 0;
}

__global__ void k_zero_i(int* p, int n) {
  int i = blockIdx.x*blockDim.x + threadIdx.x;
  if (i < n) p[i] = 0;
}

__global__ void k_count(const int* __restrict__ rows, int nnz, int* cnt) {
  int i = blockIdx.x*blockDim.x + threadIdx.x;
  if (i < nnz) atomicAdd(&cnt[rows[i]], 1);
}

// single-block warp-shuffle exclusive scan
__global__ void __launch_bounds__(1024)
k_scan(const int* __restrict__ cnt, int* __restrict__ off,
       int* __restrict__ cur, int n) {
  __shared__ int warptot[32];
  int t = threadIdx.x;
  int lane = t & 31, w = t >> 5;
  int per = (n + 1023) / 1024;
  int beg = t * per, end = min(n, beg + per);
  int s = 0;
  for (int i = beg; i < end; ++i) s += cnt[i];
  int v = s;
  #pragma unroll
  for (int o = 1; o < 32; o <<= 1) {
    int u = __shfl_up_sync(0xffffffffu, v, o);
    if (lane >= o) v += u;
  }
  if (lane == 31) warptot[w] = v;
  __syncthreads();
  if (w == 0) {
    int x = warptot[lane];
    #pragma unroll
    for (int o = 1; o < 32; o <<= 1) {
      int u = __shfl_up_sync(0xffffffffu, x, o);
      if (lane >= o) x += u;
    }
    warptot[lane] = x;
  }
  __syncthreads();
  int run = (w ? warptot[w-1] : 0) + v - s;
  for (int i = beg; i < end; ++i) {
    int c = cnt[i];
    off[i] = run; cur[i] = run;
    run += c;
  }
  if (t == 0) off[n] = warptot[31];
}

__global__ void k_scatter(const int* __restrict__ rows, const int* __restrict__ cols,
                          const float* __restrict__ vals, int nnz,
                          int* cur, int* __restrict__ scol, float* __restrict__ sval) {
  int i = blockIdx.x*blockDim.x + threadIdx.x;
  if (i < nnz) {
    int r = rows[i];
    int p = atomicAdd(&cur[r], 1);
    scol[p] = cols[i];
    sval[p] = vals[i];
  }
}

// CSR SpMM: warp per row, lane per dim, MLP-4 batched loads
__global__ void k_spmm(const int* __restrict__ off, const int* __restrict__ scol,
                       const float* __restrict__ sval, const float* __restrict__ x,
                       float* __restrict__ y, int nrows) {
  int row = blockIdx.x*8 + (threadIdx.x >> 5);
  int lane = threadIdx.x & 31;
  if (row >= nrows) return;
  int s = off[row], e = off[row+1];
  float acc = 0.f;
  int p = s;
  for (; p + 4 <= e; p += 4) {
    int c0 = __ldg(&scol[p]),   c1 = __ldg(&scol[p+1]);
    int c2 = __ldg(&scol[p+2]), c3 = __ldg(&scol[p+3]);
    float v0 = __ldg(&sval[p]),   v1 = __ldg(&sval[p+1]);
    float v2 = __ldg(&sval[p+2]), v3 = __ldg(&sval[p+3]);
    float x0 = x[c0*D + lane], x1 = x[c1*D + lane];
    float x2 = x[c2*D + lane], x3 = x[c3*D + lane];
    acc = fmaf(v0, x0, acc); acc = fmaf(v1, x1, acc);
    acc = fmaf(v2, x2, acc); acc = fmaf(v3, x3, acc);
  }
  for (; p < e; ++p)
    acc = fmaf(__ldg(&sval[p]), x[__ldg(&scol[p])*D + lane], acc);
  y[row*D + lane] = acc;
}

__global__ void k_mean_ui() {
  int i = blockIdx.x*blockDim.x + threadIdx.x;
  if (i >= UI_N*D) return;
  float m = 0.25f*(d_ui0[i] + d_ui1[i] + d_ui2[i] + d_ui3[i]);
  if (i < U_N*D) d_uemean[i] = m;
  else d_iemean[i - U_N*D] = m;
}

__global__ void k_mean_gi() {
  int i = blockIdx.x*blockDim.x + threadIdx.x;
  if (i < G_N*D)
    d_gemb[i] = 0.25f*(d_gi0[i] + d_l1[i] + d_gi2[i] + d_l3[i]);
  if (i < I_N*D) {
    int j = G_N*D + i;
    d_iemb[i] = 0.25f*(d_gi0[j] + d_gi1[j] + d_gi2[j] + d_gi3[j]);
  }
}

// ----------------- dense GEMM: Parts[y][N,32] = A[N, kslice_y] @ X[kslice_y, 32] -----------------
__device__ __forceinline__ void cpa16(uint32_t dst, const void* src, int bytes) {
  asm volatile("cp.async.cg.shared.global [%0], [%1], 16, %2;"
               :: "r"(dst), "l"(src), "r"(bytes));
}
__device__ __forceinline__ void cpa_commit() {
  asm volatile("cp.async.commit_group;");
}
__device__ __forceinline__ void cpa_wait1() {
  asm volatile("cp.async.wait_group 1;");
}

extern "C" __global__ void __launch_bounds__(256, 2)
k_gemm(const float* __restrict__ A, const float* __restrict__ X,
       float* __restrict__ Pbase, size_t pstride, int N, int K) {
  extern __shared__ float smem[];
  float* As = smem;                         // [2][BR][ASTRIDE]
  float* Xs = smem + 2*BR*ASTRIDE;          // [2][32][32]

  int tid = threadIdx.x;
  int g = tid & 63, dg = tid >> 6;
  int rowbase = blockIdx.x * BR;
  int ks = gridDim.y;
  int kchunk = (K + ks - 1) / ks;
  int kbeg = blockIdx.y * kchunk;
  int kend = min(K, kbeg + kchunk);
  int nch = (kend - kbeg + 31) >> 5;

  uint32_t as_u32, xs_u32;
  {
    uint32_t base;
    asm("{ .reg .u64 t; cvta.to.shared.u64 t, %1; cvt.u32.u64 %0, t; }"
        : "=r"(base) : "l"(smem));
    as_u32 = base;
    xs_u32 = base + 2*BR*ASTRIDE*4;
  }

  unsigned long long acc[4][4];
  #pragma unroll
  for (int j = 0; j < 4; ++j)
    #pragma unroll
    for (int p = 0; p < 4; ++p) acc[j][p] = 0ULL;

  auto load_chunk = [&](int b, int k0) {
    #pragma unroll
    for (int s = 0; s < 8; ++s) {
      int id = tid + 256*s;
      int row = id >> 3, c = id & 7;
      int gr = rowbase + row;
      int kk = k0 + 4*c;
      int vb = 0;
      const float* src = A;
      if (gr < N && kk < kend) {
        vb = min(4, kend - kk) * 4;
        src = A + (size_t)gr*K + kk;
      }
      cpa16(as_u32 + (uint32_t)(b*BR*ASTRIDE + row*ASTRIDE + 4*c)*4, src, vb);
    }
    {
      int kk = tid >> 3, c = tid & 7;
      int gk = k0 + kk;
      int vb = 0;
      const float* src = X;
      if (gk < kend) { vb = 16; src = X + (size_t)gk*D + 4*c; }
      cpa16(xs_u32 + (uint32_t)(b*32*32 + kk*32 + 4*c)*4, src, vb);
    }
  };

  if (nch > 0) load_chunk(0, kbeg);
  cpa_commit();

  for (int i = 0; i < nch; ++i) {
    if (i + 1 < nch) load_chunk((i+1) & 1, kbeg + (i+1)*32);
    cpa_commit();
    cpa_wait1();
    __syncthreads();

    const float* Ab = As + (i & 1)*BR*ASTRIDE;
    const float* Xb = Xs + (i & 1)*32*32;

    #pragma unroll
    for (int kk4 = 0; kk4 < 8; ++kk4) {
      float4 af[4];
      #pragma unroll
      for (int j = 0; j < 4; ++j)
        af[j] = *reinterpret_cast<const float4*>(&Ab[(g + 64*j)*ASTRIDE + kk4*4]);
      #pragma unroll
      for (int t = 0; t < 4; ++t) {
        int kk = kk4*4 + t;
        ulonglong2 x01 = *reinterpret_cast<const ulonglong2*>(&Xb[kk*32 + dg*8]);
        ulonglong2 x23 = *reinterpret_cast<const ulonglong2*>(&Xb[kk*32 + dg*8 + 4]);
        #pragma unroll
        for (int j = 0; j < 4; ++j) {
          float a = (t == 0) ? af[j].x : (t == 1) ? af[j].y : (t == 2) ? af[j].z : af[j].w;
          unsigned long long aa;
          asm("mov.b64 %0, {%1, %1};" : "=l"(aa) : "f"(a));
          asm("fma.rn.f32x2 %0, %1, %2, %0;" : "+l"(acc[j][0]) : "l"(aa), "l"(x01.x));
          asm("fma.rn.f32x2 %0, %1, %2, %0;" : "+l"(acc[j][1]) : "l"(aa), "l"(x01.y));
          asm("fma.rn.f32x2 %0, %1, %2, %0;" : "+l"(acc[j][2]) : "l"(aa), "l"(x23.x));
          asm("fma.rn.f32x2 %0, %1, %2, %0;" : "+l"(acc[j][3]) : "l"(aa), "l"(x23.y));
        }
      }
    }
    __syncthreads();
  }

  float* P = Pbase + (size_t)blockIdx.y * pstride;
  #pragma unroll
  for (int j = 0; j < 4; ++j) {
    int r = rowbase + g + 64*j;
    if (r < N) {
      ulonglong2 v0; v0.x = acc[j][0]; v0.y = acc[j][1];
      ulonglong2 v1; v1.x = acc[j][2]; v1.y = acc[j][3];
      *reinterpret_cast<ulonglong2*>(&P[(size_t)r*D + dg*8])     = v0;
      *reinterpret_cast<ulonglong2*>(&P[(size_t)r*D + dg*8 + 4]) = v1;
    }
  }
}

// reduce ks partials (+ up to two extra addends) into dst
__global__ void k_red(float* __restrict__ dst, const float* __restrict__ b0,
                      const float* __restrict__ b1, const float* __restrict__ parts,
                      size_t pstride, int n, int ks) {
  int i = blockIdx.x*blockDim.x + threadIdx.x;
  if (i >= n) return;
  float s = 0.f;
  for (int p = 0; p < ks; ++p) s += parts[(size_t)p*pstride + i];
  if (b0) s += b0[i];
  if (b1) s += b1[i];
  dst[i] = s;
}

__global__ void k_gul(const int* __restrict__ gu, const float* __restrict__ gm) {
  int g = blockIdx.x*8 + (threadIdx.x >> 5);
  int lane = threadIdx.x & 31;
  if (g >= G_N) return;
  float acc = 0.f;
  #pragma unroll
  for (int l = 0; l < LMEM; ++l) {
    int u = __ldg(&gu[g*LMEM + l]);
    float m = __ldg(&gm[g*LMEM + l]);
    acc = fmaf(m, d_accu[u*D + lane], acc);
  }
  d_gul[g*D + lane] = acc;
}

__global__ void k_gate(const float* __restrict__ w1, const float* __restrict__ b1,
                       const float* __restrict__ w2, const float* __restrict__ b2) {
  int row = blockIdx.x*8 + (threadIdx.x >> 5);
  int lane = threadIdx.x & 31;
  if (row >= 2*G_N) return;
  const float* x = (row < G_N) ? &d_gemb[row*D] : &d_gul[(row - G_N)*D];
  float xv = x[lane];
  float h = b1[lane];
  #pragma unroll
  for (int k = 0; k < 32; ++k) {
    float xk = __shfl_sync(0xffffffffu, xv, k);
    h = fmaf(xk, w1[k*D + lane], h);
  }
  h = fmaxf(h, 0.f);
  float s = h * w2[lane];
  #pragma unroll
  for (int o = 16; o > 0; o >>= 1) s += __shfl_xor_sync(0xffffffffu, s, o);
  if (lane == 0) d_wgt[row] = 1.f/(1.f + expf(-(s + b2[0])));
}

__global__ void k_gfin() {
  int i = blockIdx.x*blockDim.x + threadIdx.x;
  if (i >= G_N*D) return;
  int g = i / D;
  d_gfin[i] = d_wgt[g]*d_gemb[i] + d_wgt[G_N + g]*d_gul[i];
}

__global__ void k_pred(const int* __restrict__ gin, const int* __restrict__ iin,
                       const float* __restrict__ w1, const float* __restrict__ b1,
                       const float* __restrict__ w2, const float* __restrict__ b2,
                       float* __restrict__ out) {
  int b = blockIdx.x*8 + (threadIdx.x >> 5);
  int lane = threadIdx.x & 31;
  if (b >= B_N) return;
  float e = d_gfin[gin[b]*D + lane] * d_iacc[iin[b]*D + lane];
  float z = 0.f;
  #pragma unroll
  for (int j = 0; j < 8; ++j) {
    float v = e * w1[lane*8 + j];
    #pragma unroll
    for (int o = 16; o > 0; o >>= 1) v += __shfl_xor_sync(0xffffffffu, v, o);
    if (lane == 0) z += fmaxf(v + b1[j], 0.f) * w2[j];
  }
  if (lane == 0) out[b] = 1.f/(1.f + expf(-(z + b2[0])));
}

// ----------------- host -----------------
template <typename T>
static T* symaddr(const void* sym) {
  void* p = nullptr;
  cudaGetSymbolAddress(&p, sym);
  return (T*)p;
}

extern "C" void kernel_launch(void* const* d_in, const int* in_sizes, int n_in,
                              void* d_out, int out_size) {
  const int*   gin       = (const int*)d_in[0];
  const int*   iin       = (const int*)d_in[1];
  const float* user_emb  = (const float*)d_in[2];
  const float* group_emb = (const float*)d_in[3];
  const float* item_emb  = (const float*)d_in[4];
  const int*   ui_rows   = (const int*)d_in[5];
  const int*   ui_cols   = (const int*)d_in[6];
  const float* ui_vals   = (const float*)d_in[7];
  const int*   gi_rows   = (const int*)d_in[8];
  const int*   gi_cols   = (const int*)d_in[9];
  const float* gi_vals   = (const float*)d_in[10];
  const float* ov_user   = (const float*)d_in[11];
  const float* ov_item   = (const float*)d_in[12];
  const int*   agu       = (const int*)d_in[13];
  const float* agm       = (const float*)d_in[14];
  const float* gate_w1   = (const float*)d_in[15];
  const float* gate_b1   = (const float*)d_in[16];
  const float* gate_w2   = (const float*)d_in[17];
  const float* gate_b2   = (const float*)d_in[18];
  const float* pred_w1   = (const float*)d_in[19];
  const float* pred_b1   = (const float*)d_in[20];
  const float* pred_w2   = (const float*)d_in[21];
  const float* pred_b2   = (const float*)d_in[22];
  float* out = (float*)d_out;

  cudaFuncSetAttribute(k_gemm, cudaFuncAttributeMaxDynamicSharedMemorySize, SMEM_GEMM);

  float *p_ui0 = symaddr<float>(d_ui0), *p_ui1 = symaddr<float>(d_ui1);
  float *p_ui2 = symaddr<float>(d_ui2), *p_ui3 = symaddr<float>(d_ui3);
  float *p_gi0 = symaddr<float>(d_gi0), *p_gi1 = symaddr<float>(d_gi1);
  float *p_gi2 = symaddr<float>(d_gi2), *p_gi3 = symaddr<float>(d_gi3);
  float *p_cat  = symaddr<float>(d_cat), *p_cat2 = symaddr<float>(d_cat2);
  float *p_l1  = symaddr<float>(d_l1),  *p_l3  = symaddr<float>(d_l3);
  int *p_cnt  = symaddr<int>(d_cnt),  *p_off  = symaddr<int>(d_off),  *p_cur  = symaddr<int>(d_cur);
  int *p_cnt2 = symaddr<int>(d_cnt2), *p_off2 = symaddr<int>(d_off2), *p_cur2 = symaddr<int>(d_cur2);
  int *p_scol = symaddr<int>(d_scol), *p_scol2 = symaddr<int>(d_scol2);
  float *p_sval = symaddr<float>(d_sval), *p_sval2 = symaddr<float>(d_sval2);
  float *p_uemean = symaddr<float>(d_uemean), *p_iemean = symaddr<float>(d_iemean);
  float *p_iemb = symaddr<float>(d_iemb);
  float *p_parts = symaddr<float>(d_parts), *p_parts2 = symaddr<float>(d_parts2);
  float *p_t1 = symaddr<float>(d_t1), *p_accu = symaddr<float>(d_accu);
  float *p_it1 = symaddr<float>(d_it1), *p_iacc = symaddr<float>(d_iacc);

  const size_t PSU = (size_t)U_N * D;
  const size_t PSI = (size_t)I_N * D;
  dim3 gemm_u(CDIV(U_N, BR), KSU);
  dim3 gemm_i(CDIV(I_N, BR), KSI);

  // second stream + events (leaked; kernel_launch called only a couple of times)
  cudaStream_t s1;
  cudaStreamCreateWithFlags(&s1, cudaStreamNonBlocking);
  cudaEvent_t ev_fork, ev_gicsr, ev_l1, ev_A, ev_mg, ev_C2;
  cudaEventCreateWithFlags(&ev_fork,  cudaEventDisableTiming);
  cudaEventCreateWithFlags(&ev_gicsr, cudaEventDisableTiming);
  cudaEventCreateWithFlags(&ev_l1,    cudaEventDisableTiming);
  cudaEventCreateWithFlags(&ev_A,     cudaEventDisableTiming);
  cudaEventCreateWithFlags(&ev_mg,    cudaEventDisableTiming);
  cudaEventCreateWithFlags(&ev_C2,    cudaEventDisableTiming);

  cudaEventRecord(ev_fork, 0);

  // ---- segment A1 (s0): launches #1..#4; #4 = representative GEMM for ncu ----
  k_copy_zero<<<CDIV((U_N+I_N)*D,256),256>>>(user_emb, U_N*D, item_emb, I_N*D, p_ui0, p_cnt, UI_N);
  k_count<<<CDIV(NNZ_UI,256),256>>>(ui_rows, NNZ_UI, p_cnt);
  k_scan<<<1,1024>>>(p_cnt, p_off, p_cur, UI_N);
  // HOOK (launch #4): real steady-state GEMM on ov_user, truncated K; output overwritten later.
  k_gemm<<<gemm_u,256,SMEM_GEMM>>>(ov_user, ov_user, p_parts, PSU, U_N, 1536);

  // ---- segment B (s1): GI CSR build + l1 (independent of stage A) ----
  cudaStreamWaitEvent(s1, ev_fork, 0);
  k_zero_i<<<CDIV(GI_N,256),256,0,s1>>>(p_cnt2, GI_N);
  k_count<<<CDIV(NNZ_GI,256),256,0,s1>>>(gi_rows, NNZ_GI, p_cnt2);
  k_scan<<<1,1024,0,s1>>>(p_cnt2, p_off2, p_cur2, GI_N);
  k_scatter<<<CDIV(NNZ_GI,256),256,0,s1>>>(gi_rows, gi_cols, gi_vals, NNZ_GI, p_cur2, p_scol2, p_sval2);
  cudaEventRecord(ev_gicsr, s1);
  k_copy2<<<CDIV(GI_N*D,256),256,0,s1>>>(group_emb, G_N*D, item_emb, I_N*D, p_cat);
  k_spmm<<<CDIV(G_N,8),256,0,s1>>>(p_off2, p_scol2, p_sval2, p_cat, p_l1, G_N);
  cudaEventRecord(ev_l1, s1);

  // ---- segment A2 (s0): UI CSR + propagation ----
  k_scatter<<<CDIV(NNZ_UI,256),256>>>(ui_rows, ui_cols, ui_vals, NNZ_UI, p_cur, p_scol, p_sval);
  k_spmm<<<CDIV(UI_N,8),256>>>(p_off, p_scol, p_sval, p_ui0, p_ui1, UI_N);
  k_spmm<<<CDIV(UI_N,8),256>>>(p_off, p_scol, p_sval, p_ui1, p_ui2, UI_N);
  k_spmm<<<CDIV(UI_N,8),256>>>(p_off, p_scol, p_sval, p_ui2, p_ui3, UI_N);
  k_mean_ui<<<CDIV(UI_N*D,256),256>>>();
  cudaEventRecord(ev_A, 0);

  // ---- segment C (s1): user social GEMMs + group pooling ----
  cudaStreamWaitEvent(s1, ev_A, 0);
  k_gemm<<<gemm_u,256,SMEM_GEMM,s1>>>(ov_user, p_uemean, p_parts, PSU, U_N, U_N);
  k_red<<<CDIV(U_N*D,256),256,0,s1>>>(p_t1, nullptr, nullptr, p_parts, PSU, U_N*D, KSU);
  k_gemm<<<gemm_u,256,SMEM_GEMM,s1>>>(ov_user, p_t1, p_parts, PSU, U_N, U_N);
  k_red<<<CDIV(U_N*D,256),256,0,s1>>>(p_accu, p_uemean, p_t1, p_parts, PSU, U_N*D, KSU);
  k_gul<<<CDIV(G_N,8),256,0,s1>>>(agu, agm);

  // ---- segment D (s0): group-item propagation (overlaps C) ----
  k_copy2<<<CDIV(GI_N*D,256),256>>>(group_emb, G_N*D, p_iemean, I_N*D, p_gi0);
  cudaStreamWaitEvent(0, ev_gicsr, 0);
  k_spmm<<<CDIV(GI_N,8),256>>>(p_off2, p_scol2, p_sval2, p_gi0, p_gi1, GI_N);
  k_spmm<<<CDIV(GI_N,8),256>>>(p_off2, p_scol2, p_sval2, p_gi1, p_gi2, GI_N);
  k_spmm<<<CDIV(GI_N,8),256>>>(p_off2, p_scol2, p_sval2, p_gi2, p_gi3, GI_N);
  k_copy2<<<CDIV(GI_N*D,256),256>>>(group_emb, G_N*D, p_ui2 + U_N*D, I_N*D, p_cat2);
  k_spmm<<<CDIV(G_N,8),256>>>(p_off2, p_scol2, p_sval2, p_cat2, p_l3, G_N);
  cudaStreamWaitEvent(0, ev_l1, 0);
  k_mean_gi<<<CDIV(I_N*D,256),256>>>();
  cudaEventRecord(ev_mg, 0);

  // ---- segment E (s0): item social GEMMs ----
  k_gemm<<<gemm_i,256,SMEM_GEMM>>>(ov_item, p_iemb, p_parts2, PSI, I_N, I_N);
  k_red<<<CDIV(I_N*D,256),256>>>(p_it1, nullptr, nullptr, p_parts2, PSI, I_N*D, KSI);
  k_gemm<<<gemm_i,256,SMEM_GEMM>>>(ov_item, p_it1, p_parts2, PSI, I_N, I_N);
  k_red<<<CDIV(I_N*D,256),256>>>(p_iacc, p_iemb, p_it1, p_parts2, PSI, I_N*D, KSI);

  // ---- segment F (s1): gate (needs gemb from s0, gul from s1) ----
  cudaStreamWaitEvent(s1, ev_mg, 0);
  k_gate<<<CDIV(2*G_N,8),256,0,s1>>>(gate_w1, gate_b1, gate_w2, gate_b2);
  k_gfin<<<CDIV(G_N*D,256),256,0,s1>>>();
  cudaEventRecord(ev_C2, s1);

  // ---- segment G (s0): predict (joins s1) ----
  cudaStreamWaitEvent(0, ev_C2, 0);
  k_pred<<<CDIV(B_N,8),256>>>(gin, iin, pred_w1, pred_b1, pred_w2, pred_b2, out);
}